// round 6
// baseline (speedup 1.0000x reference)
#include <cuda_runtime.h>
#include <cstddef>

// One warp per row of 1024 floats, persistent grid-stride over rows.
// Thread owns 32 elements i = 128k + 4*lane + b, held as v[c], c = 4k+b.
//   c bits {0,1} = i bits {0,1};  c bits {2,3,4} = i bits {7,8,9}
// FWHT1024 = FWHT32 over c-bits  ∘  FWHT32 over lane-bits (i bits 2..6).
// Lane-bit half via conflict-free 32x32 padded-SMEM transpose. No shuffles.
// scale/shift read per-row via __ldg (4KB each -> L1-resident), keeping
// registers low enough for 3 CTAs/SM (24 warps) of latency hiding.

#define NWARPS 8

__global__ void __launch_bounds__(256, 3)
fwht1024_kernel(const float* __restrict__ x,
                const float* __restrict__ scale,
                const float* __restrict__ shift,
                float* __restrict__ out,
                int nrows, int warp_stride)
{
    __shared__ float xch[NWARPS][32 * 33];   // 4224 B per warp, 33.8 KB/block
    const int wlocal = threadIdx.x >> 5;
    const int lane   = threadIdx.x & 31;
    float* __restrict__ sm = xch[wlocal];

    const float4* __restrict__ sc4 = reinterpret_cast<const float4*>(scale);
    const float4* __restrict__ sh4 = reinterpret_cast<const float4*>(shift);
    const float inv = 0.03125f;              // 1/sqrt(1024)

    const int wid = blockIdx.x * NWARPS + wlocal;

    for (int row = wid; row < nrows; row += warp_stride) {
        const float4* __restrict__ xin =
            reinterpret_cast<const float4*>(x) + (size_t)row * 256u;
        float4* __restrict__ xo =
            reinterpret_cast<float4*>(out) + (size_t)row * 256u;

        float v[32];

        // coalesced streaming load: float4 index 32k+lane
        #pragma unroll
        for (int k = 0; k < 8; k++) {
            float4 t = __ldcs(&xin[k * 32 + lane]);
            v[4*k+0] = t.x; v[4*k+1] = t.y; v[4*k+2] = t.z; v[4*k+3] = t.w;
        }

        // ---- FWHT32 over register index (element bits 0,1,7,8,9) ----
        #pragma unroll
        for (int m = 1; m < 32; m <<= 1) {
            #pragma unroll
            for (int p = 0; p < 32; p++) {
                if ((p & m) == 0) {
                    float u = v[p], w = v[p | m];
                    v[p]     = u + w;
                    v[p | m] = u - w;
                }
            }
        }

        // ---- transpose: write sm[lane*33+c] (bank lane+c: CF),
        //                 read  sm[j*33+lane] (consecutive: CF) ----
        #pragma unroll
        for (int c = 0; c < 32; c++) sm[lane * 33 + c] = v[c];
        __syncwarp();
        #pragma unroll
        for (int j = 0; j < 32; j++) v[j] = sm[j * 33 + lane];

        // ---- FWHT32 over new register index (element bits 2..6) ----
        #pragma unroll
        for (int m = 1; m < 32; m <<= 1) {
            #pragma unroll
            for (int p = 0; p < 32; p++) {
                if ((p & m) == 0) {
                    float u = v[p], w = v[p | m];
                    v[p]     = u + w;
                    v[p | m] = u - w;
                }
            }
        }

        // ---- transpose back (each thread overwrites exactly the words it
        //      just read -> no sync needed before the writes) ----
        #pragma unroll
        for (int j = 0; j < 32; j++) sm[j * 33 + lane] = v[j];
        __syncwarp();
        #pragma unroll
        for (int c = 0; c < 32; c++) v[c] = sm[lane * 33 + c];

        // ---- epilogue: scale/shift from L1, coalesced streaming store ----
        #pragma unroll
        for (int k = 0; k < 8; k++) {
            float4 s4 = __ldg(&sc4[k * 32 + lane]);
            float4 h4 = __ldg(&sh4[k * 32 + lane]);
            float4 r;
            r.x = fmaf(s4.x * inv, v[4*k+0], h4.x);
            r.y = fmaf(s4.y * inv, v[4*k+1], h4.y);
            r.z = fmaf(s4.z * inv, v[4*k+2], h4.z);
            r.w = fmaf(s4.w * inv, v[4*k+3], h4.w);
            __stcs(&xo[k * 32 + lane], r);
        }
        // next-iter transpose writes touch only words this thread last read: safe
    }
}

extern "C" void kernel_launch(void* const* d_in, const int* in_sizes, int n_in,
                              void* d_out, int out_size)
{
    const float* x     = (const float*)d_in[0];
    const float* scale = (const float*)d_in[1];
    const float* shift = (const float*)d_in[2];
    float* out = (float*)d_out;

    const int nrows = in_sizes[0] / 1024;

    int sms = 148;
    cudaDeviceGetAttribute(&sms, cudaDevAttrMultiProcessorCount, 0);
    const int blocks = sms * 3;                 // 3 CTAs/SM (regs<=85, smem 101KB)
    const int warp_stride = blocks * NWARPS;    // persistent grid-stride

    fwht1024_kernel<<<blocks, 32 * NWARPS>>>(x, scale, shift, out,
                                             nrows, warp_stride);
}